// round 5
// baseline (speedup 1.0000x reference)
#include <cuda_runtime.h>
#include <cuda_fp16.h>
#include <cstdint>

// ---------------------------------------------------------------------------
// Problem dims (fixed by the dataset)
// ---------------------------------------------------------------------------
#define NTOK 8192          // B*S tokens
#define DIM  1024          // model dim
#define HID  4096          // hidden dim
#define NE   8             // experts
#define CAP  8192          // per-expert token capacity (max possible)

#define BM 128
#define BN 128
#define BK 64
#define ST 4               // cp.async pipeline stages
#define LDA (BK + 8)       // 72 halves (144B rows -> bank stride 4, conflict-free)
#define LDB (BN + 8)       // 136 halves (272B rows -> bank stride 4, conflict-free)

// ---------------------------------------------------------------------------
// Scratch (static __device__ arrays; allocation-free kernel_launch)
// ---------------------------------------------------------------------------
__device__ int    g_cnt[NE];
__device__ int    g_ptok[NE * CAP];
__device__ float  g_pgate[NE * CAP];
__device__ __half g_X  [(size_t)NE * CAP * DIM];   // gathered tokens, fp16
__device__ __half g_W1h[(size_t)NE * DIM * HID];   // W1 fp16, layout [E][D][H]
__device__ __half g_W2h[(size_t)NE * HID * DIM];   // W2 fp16, layout [E][H][D]
__device__ __half g_Hb [(size_t)NE * CAP * HID];   // gelu(x@W1+b1), fp16

// ---------------------------------------------------------------------------
// PTX helpers (baseline compute_103-legal only: cp.async / ldmatrix / mma.sync)
// ---------------------------------------------------------------------------
__device__ __forceinline__ uint32_t smem_u32(const void* p) {
    uint32_t a;
    asm("{ .reg .u64 t; cvta.to.shared.u64 t, %1; cvt.u32.u64 %0, t; }"
        : "=r"(a) : "l"(p));
    return a;
}

__device__ __forceinline__ void cp16(uint32_t smaddr, const void* g) {
    asm volatile("cp.async.cg.shared.global [%0], [%1], 16;"
                 :: "r"(smaddr), "l"(g));
}
#define CP_COMMIT() asm volatile("cp.async.commit_group;" ::: "memory")
#define CP_WAIT(n)  asm volatile("cp.async.wait_group %0;" :: "n"(n) : "memory")

__device__ __forceinline__ void ldsm_x4(uint32_t* r, uint32_t addr) {
    asm volatile("ldmatrix.sync.aligned.m8n8.x4.shared.b16 {%0,%1,%2,%3}, [%4];"
                 : "=r"(r[0]), "=r"(r[1]), "=r"(r[2]), "=r"(r[3]) : "r"(addr));
}
__device__ __forceinline__ void ldsm_x4_t(uint32_t* r, uint32_t addr) {
    asm volatile("ldmatrix.sync.aligned.m8n8.x4.trans.shared.b16 {%0,%1,%2,%3}, [%4];"
                 : "=r"(r[0]), "=r"(r[1]), "=r"(r[2]), "=r"(r[3]) : "r"(addr));
}

// fp16-accumulator MMA: D(f16x2 pair) = A*B + C(f16x2 pair)
__device__ __forceinline__ void mma16816_f16(uint32_t* c, const uint32_t* a,
                                             const uint32_t* b) {
    asm volatile(
        "mma.sync.aligned.m16n8k16.row.col.f16.f16.f16.f16 "
        "{%0,%1}, {%2,%3,%4,%5}, {%6,%7}, {%0,%1};"
        : "+r"(c[0]), "+r"(c[1])
        : "r"(a[0]), "r"(a[1]), "r"(a[2]), "r"(a[3]), "r"(b[0]), "r"(b[1]));
}

// tanh-approximate GELU (JAX default): x * sigmoid(2u), u = 0.79788(x+0.044715x^3)
__device__ __forceinline__ float gelu_f(float v) {
    float u2 = 2.0f * 0.7978845608028654f * (v + 0.044715f * v * v * v);
    u2 = fminf(fmaxf(u2, -30.0f), 30.0f);
    float t = __expf(u2);
    return v * __fdividef(t, t + 1.0f);
}

// ---------------------------------------------------------------------------
// Kernel 1: zero output + counters
// ---------------------------------------------------------------------------
__global__ void zero_kernel(float* __restrict__ out, size_t n4) {
    size_t i = (size_t)blockIdx.x * blockDim.x + threadIdx.x;
    float4 z = make_float4(0.f, 0.f, 0.f, 0.f);
    size_t stride = (size_t)gridDim.x * blockDim.x;
    for (; i < n4; i += stride) ((float4*)out)[i] = z;
    if (blockIdx.x == 0 && threadIdx.x < NE) g_cnt[threadIdx.x] = 0;
}

// ---------------------------------------------------------------------------
// Kernel 2: router — one warp per token
// ---------------------------------------------------------------------------
__global__ void router_kernel(const float* __restrict__ x,
                              const float* __restrict__ Wr) {
    int gwarp = (blockIdx.x * blockDim.x + threadIdx.x) >> 5;
    int lane = threadIdx.x & 31;
    if (gwarp >= NTOK) return;
    const float* xr = x + (size_t)gwarp * DIM;
    float a0 = 0, a1 = 0, a2 = 0, a3 = 0, a4 = 0, a5 = 0, a6 = 0, a7 = 0;
    for (int d = lane; d < DIM; d += 32) {
        float xv = xr[d];
        const float4* w = (const float4*)(Wr + (size_t)d * NE);
        float4 w0 = w[0], w1 = w[1];
        a0 += xv * w0.x; a1 += xv * w0.y; a2 += xv * w0.z; a3 += xv * w0.w;
        a4 += xv * w1.x; a5 += xv * w1.y; a6 += xv * w1.z; a7 += xv * w1.w;
    }
#pragma unroll
    for (int o = 16; o > 0; o >>= 1) {
        a0 += __shfl_xor_sync(0xffffffffu, a0, o);
        a1 += __shfl_xor_sync(0xffffffffu, a1, o);
        a2 += __shfl_xor_sync(0xffffffffu, a2, o);
        a3 += __shfl_xor_sync(0xffffffffu, a3, o);
        a4 += __shfl_xor_sync(0xffffffffu, a4, o);
        a5 += __shfl_xor_sync(0xffffffffu, a5, o);
        a6 += __shfl_xor_sync(0xffffffffu, a6, o);
        a7 += __shfl_xor_sync(0xffffffffu, a7, o);
    }
    if (lane == 0) {
        float p[8] = {a0, a1, a2, a3, a4, a5, a6, a7};
        float m = p[0];
#pragma unroll
        for (int e = 1; e < 8; e++) m = fmaxf(m, p[e]);
        float s = 0.f;
#pragma unroll
        for (int e = 0; e < 8; e++) { p[e] = expf(p[e] - m); s += p[e]; }
        float inv = 1.0f / s;
#pragma unroll
        for (int e = 0; e < 8; e++) p[e] *= inv;
        int i1 = 0; float v1 = p[0];
#pragma unroll
        for (int e = 1; e < 8; e++) if (p[e] > v1) { v1 = p[e]; i1 = e; }
        int i2 = -1; float v2 = -1.0f;
#pragma unroll
        for (int e = 0; e < 8; e++)
            if (e != i1 && p[e] > v2) { v2 = p[e]; i2 = e; }
        int s1 = atomicAdd(&g_cnt[i1], 1);
        g_ptok[i1 * CAP + s1] = gwarp; g_pgate[i1 * CAP + s1] = v1;
        int s2 = atomicAdd(&g_cnt[i2], 1);
        g_ptok[i2 * CAP + s2] = gwarp; g_pgate[i2 * CAP + s2] = v2;
    }
}

// ---------------------------------------------------------------------------
// Kernel 3: gather tokens -> fp16 per-expert buffer
// ---------------------------------------------------------------------------
__global__ void gather_kernel(const float* __restrict__ x) {
    int e = blockIdx.y, slot = blockIdx.x;
    if (slot >= g_cnt[e]) return;
    int t = g_ptok[e * CAP + slot];
    const float4* src = (const float4*)(x + (size_t)t * DIM);
    uint2* dst = (uint2*)(g_X + ((size_t)e * CAP + slot) * DIM);
    int i = threadIdx.x;                 // 256 threads * 4 floats = 1024
    float4 v = src[i];
    __half2 h0 = __floats2half2_rn(v.x, v.y);
    __half2 h1 = __floats2half2_rn(v.z, v.w);
    uint2 u;
    u.x = *reinterpret_cast<unsigned*>(&h0);
    u.y = *reinterpret_cast<unsigned*>(&h1);
    dst[i] = u;
}

// ---------------------------------------------------------------------------
// Kernel 4: fp32 -> fp16 weight convert (no transpose: ldmatrix.trans consumes
// native [K,N] layout). Converts both W1 and W2 (same element count).
// ---------------------------------------------------------------------------
__global__ void convert_w_kernel(const float* __restrict__ W1,
                                 const float* __restrict__ W2) {
    size_t n4 = (size_t)NE * DIM * HID / 4;
    size_t stride = (size_t)gridDim.x * blockDim.x;
    for (size_t i = (size_t)blockIdx.x * blockDim.x + threadIdx.x; i < n4; i += stride) {
        float4 v1 = ((const float4*)W1)[i];
        float4 v2 = ((const float4*)W2)[i];
        __half2 a0 = __floats2half2_rn(v1.x, v1.y);
        __half2 a1 = __floats2half2_rn(v1.z, v1.w);
        __half2 b0 = __floats2half2_rn(v2.x, v2.y);
        __half2 b1 = __floats2half2_rn(v2.z, v2.w);
        uint2 u1, u2;
        u1.x = *reinterpret_cast<unsigned*>(&a0);
        u1.y = *reinterpret_cast<unsigned*>(&a1);
        u2.x = *reinterpret_cast<unsigned*>(&b0);
        u2.y = *reinterpret_cast<unsigned*>(&b1);
        ((uint2*)g_W1h)[i] = u1;
        ((uint2*)g_W2h)[i] = u2;
    }
}

// ---------------------------------------------------------------------------
// Kernel 5: fp16 mma.sync GEMM, 128x128x64 tiles, 4-stage cp.async pipeline.
// fp16 accumulator chains over K=64 (4 mma), promoted to fp32 once per K-tile.
// mode 0: H = gelu(X @ W1 + b1)        (A = g_X [rows,D], B = W1h [D,H])
// mode 1: out[tok] += gate*(H @ W2+b2) (A = g_Hb [rows,H], B = W2h [H,D])
// 8 warps as 4(M) x 2(N); warp tile 32x64; 1 CTA/SM (full reg file).
// ---------------------------------------------------------------------------
struct GSmem {
    __half A[ST][BM][LDA];   // 4 * 128*72*2 = 73728 B
    __half B[ST][BK][LDB];   // 4 *  64*136*2 = 69632 B
};
#define GSMEM_BYTES ((int)sizeof(GSmem))   // 143360 B

__global__ void __launch_bounds__(256, 1)
moe_gemm_kernel(int mode, const float* __restrict__ bias, float* __restrict__ out) {
    extern __shared__ char dyn_smem[];
    GSmem& sm = *reinterpret_cast<GSmem*>(dyn_smem);

    int e = blockIdx.z;
    int cnt = g_cnt[e];
    int row0 = blockIdx.y * BM;
    if (row0 >= cnt) return;
    int valid = cnt - row0;          // rows alive in this tile (may exceed BM)
    int nb0 = blockIdx.x * BN;

    const __half* Ag; const __half* Bg;
    int lda, ldb, Kdim;
    if (mode == 0) {
        Ag = g_X   + (size_t)e * CAP * DIM + (size_t)row0 * DIM;  lda = DIM;
        Bg = g_W1h + (size_t)e * DIM * HID;                       ldb = HID;
        Kdim = DIM;
    } else {
        Ag = g_Hb  + (size_t)e * CAP * HID + (size_t)row0 * HID;  lda = HID;
        Bg = g_W2h + (size_t)e * HID * DIM;                       ldb = DIM;
        Kdim = HID;
    }

    int tid = threadIdx.x;
    int lane = tid & 31;
    int warp = tid >> 5;
    int wm = warp >> 1;              // 0..3  (M groups of 32)
    int wn = warp & 1;               // 0..1  (N groups of 64)

    float acc[2][8][4];
#pragma unroll
    for (int mi = 0; mi < 2; mi++)
#pragma unroll
        for (int nj = 0; nj < 8; nj++)
#pragma unroll
            for (int q = 0; q < 4; q++) acc[mi][nj][q] = 0.f;

    // --- cp.async stage loader: A tile 128x64 (1024 x 16B), B tile 64x128 (1024 x 16B)
    auto load_stage = [&](int kt, int s) {
#pragma unroll
        for (int i = 0; i < 4; i++) {
            int c = tid + i * 256;
            int r = c >> 3, v = c & 7;
            cp16(smem_u32(&sm.A[s][r][v * 8]),
                 Ag + (size_t)r * lda + kt * BK + v * 8);
        }
#pragma unroll
        for (int i = 0; i < 4; i++) {
            int c = tid + i * 256;
            int r = c >> 4, cc = c & 15;
            cp16(smem_u32(&sm.B[s][r][cc * 8]),
                 Bg + (size_t)(kt * BK + r) * ldb + nb0 + cc * 8);
        }
        CP_COMMIT();
    };

    int nk = Kdim / BK;              // 16 (GEMM1) or 64 (GEMM2); > ST-1 always
    // prologue: fill ST-1 stages (3 groups in flight)
#pragma unroll
    for (int p = 0; p < ST - 1; p++) load_stage(p, p);

    for (int kt = 0; kt < nk; kt++) {
        CP_WAIT(ST - 2);             // <=2 groups pending -> stage kt resident
        __syncthreads();             // also proves stage (kt-1) fully consumed
        if (kt + ST - 1 < nk) load_stage(kt + ST - 1, (kt + ST - 1) % ST);
        else                  CP_COMMIT();   // empty group keeps wait invariant
        int cur = kt % ST;

        // fp16 chain accumulators for this K-tile (zeroed per chain of K=64)
        uint32_t c16[2][8][2];
#pragma unroll
        for (int mi = 0; mi < 2; mi++)
#pragma unroll
            for (int nj = 0; nj < 8; nj++) { c16[mi][nj][0] = 0u; c16[mi][nj][1] = 0u; }

#pragma unroll
        for (int ks = 0; ks < 4; ks++) {
            uint32_t af[2][4];
#pragma unroll
            for (int mi = 0; mi < 2; mi++) {
                int r = wm * 32 + mi * 16 + (lane & 15);
                int cc = ks * 16 + ((lane >> 4) << 3);
                ldsm_x4(af[mi], smem_u32(&sm.A[cur][r][cc]));
            }
            uint32_t bf[8][2];
#pragma unroll
            for (int j = 0; j < 4; j++) {
                int kr = ks * 16 + (lane & 7) + (((lane >> 3) & 1) << 3);
                int nc = wn * 64 + j * 16 + ((lane >> 4) << 3);
                uint32_t r4[4];
                ldsm_x4_t(r4, smem_u32(&sm.B[cur][kr][nc]));
                bf[2 * j][0] = r4[0]; bf[2 * j][1] = r4[1];
                bf[2 * j + 1][0] = r4[2]; bf[2 * j + 1][1] = r4[3];
            }
#pragma unroll
            for (int mi = 0; mi < 2; mi++)
#pragma unroll
                for (int nj = 0; nj < 8; nj++)
                    mma16816_f16(c16[mi][nj], af[mi], bf[nj]);
        }

        // promote K=64 fp16 partials into fp32 accumulators (once per K-tile)
#pragma unroll
        for (int mi = 0; mi < 2; mi++)
#pragma unroll
            for (int nj = 0; nj < 8; nj++) {
                float2 f0 = __half22float2(*reinterpret_cast<__half2*>(&c16[mi][nj][0]));
                float2 f1 = __half22float2(*reinterpret_cast<__half2*>(&c16[mi][nj][1]));
                acc[mi][nj][0] += f0.x; acc[mi][nj][1] += f0.y;
                acc[mi][nj][2] += f1.x; acc[mi][nj][3] += f1.y;
            }
    }

    // --- Epilogue. acc[mi][nj]: rows wm*32+mi*16+{lane/4, +8}, cols wn*64+nj*8+(lane%4)*2+{0,1}
    if (mode == 0) {
        const float* bp = bias + (size_t)e * HID + nb0;
#pragma unroll
        for (int mi = 0; mi < 2; mi++) {
            int rb = wm * 32 + mi * 16 + (lane >> 2);
#pragma unroll
            for (int hr = 0; hr < 2; hr++) {
                int r = rb + hr * 8;
                if (r < valid) {
                    size_t rowoff = ((size_t)e * CAP + row0 + r) * HID + nb0;
#pragma unroll
                    for (int nj = 0; nj < 8; nj++) {
                        int colc = wn * 64 + nj * 8 + ((lane & 3) << 1);
                        float v0 = acc[mi][nj][hr * 2 + 0] + bp[colc];
                        float v1 = acc[mi][nj][hr * 2 + 1] + bp[colc + 1];
                        __half2 h2 = __floats2half2_rn(gelu_f(v0), gelu_f(v1));
                        *(__half2*)(g_Hb + rowoff + colc) = h2;
                    }
                }
            }
        }
    } else {
        const float* bp = bias + (size_t)e * DIM + nb0;
#pragma unroll
        for (int mi = 0; mi < 2; mi++) {
            int rb = wm * 32 + mi * 16 + (lane >> 2);
#pragma unroll
            for (int hr = 0; hr < 2; hr++) {
                int r = rb + hr * 8;
                if (r < valid) {
                    int t = g_ptok[e * CAP + row0 + r];
                    float gate = g_pgate[e * CAP + row0 + r];
                    float* orow = out + (size_t)t * DIM + nb0;
#pragma unroll
                    for (int nj = 0; nj < 8; nj++) {
                        int colc = wn * 64 + nj * 8 + ((lane & 3) << 1);
                        float v0 = acc[mi][nj][hr * 2 + 0] + bp[colc];
                        float v1 = acc[mi][nj][hr * 2 + 1] + bp[colc + 1];
                        atomicAdd(orow + colc,     gate * v0);
                        atomicAdd(orow + colc + 1, gate * v1);
                    }
                }
            }
        }
    }
}

// ---------------------------------------------------------------------------
// Launch
// ---------------------------------------------------------------------------
extern "C" void kernel_launch(void* const* d_in, const int* in_sizes, int n_in,
                              void* d_out, int out_size) {
    const float* x  = (const float*)d_in[0];
    const float* Wr = (const float*)d_in[1];
    const float* W1 = (const float*)d_in[2];
    const float* b1 = (const float*)d_in[3];
    const float* W2 = (const float*)d_in[4];
    const float* b2 = (const float*)d_in[5];
    float* out = (float*)d_out;

    static int smem_set = 0;
    if (!smem_set) {
        cudaFuncSetAttribute(moe_gemm_kernel,
                             cudaFuncAttributeMaxDynamicSharedMemorySize,
                             GSMEM_BYTES);
        smem_set = 1;
    }

    // 1. zero output + expert counters
    zero_kernel<<<2048, 256>>>(out, (size_t)NTOK * DIM / 4);
    // 2. router (one warp per token)
    router_kernel<<<NTOK / 8, 256>>>(x, Wr);
    // 3. gather tokens into per-expert fp16 buffers
    gather_kernel<<<dim3(CAP, NE), 256>>>(x);
    // 4. fp32 -> fp16 weight conversion (no transpose needed)
    convert_w_kernel<<<2048, 256>>>(W1, W2);
    // 5. GEMM1: H = gelu(X @ W1 + b1)
    moe_gemm_kernel<<<dim3(HID / BN, CAP / BM, NE), 256, GSMEM_BYTES>>>(0, b1, nullptr);
    // 6. GEMM2: out += gate * (H @ W2 + b2)
    moe_gemm_kernel<<<dim3(DIM / BN, CAP / BM, NE), 256, GSMEM_BYTES>>>(1, b2, out);
}

// round 6
// speedup vs baseline: 1.2824x; 1.2824x over previous
#include <cuda_runtime.h>
#include <cuda_fp16.h>
#include <cstdint>

// ---------------------------------------------------------------------------
// Problem dims (fixed by the dataset)
// ---------------------------------------------------------------------------
#define NTOK 8192          // B*S tokens
#define DIM  1024          // model dim
#define HID  4096          // hidden dim
#define NE   8             // experts
#define CAP  8192          // per-expert token capacity (max possible)

#define BM 128
#define BN 128
#define BK 32
#define ST 4               // cp.async pipeline stages
#define LDA (BK + 8)       // 40 halves  (80B rows, conflict-free for ldmatrix)
#define LDB (BN + 8)       // 136 halves (272B rows, conflict-free for ldmatrix)

// ---------------------------------------------------------------------------
// Scratch (static __device__ arrays; allocation-free kernel_launch)
// ---------------------------------------------------------------------------
__device__ int    g_cnt[NE];
__device__ int    g_ptok[NE * CAP];
__device__ float  g_pgate[NE * CAP];
__device__ __half g_X  [(size_t)NE * CAP * DIM];   // gathered tokens, fp16
__device__ __half g_W1h[(size_t)NE * DIM * HID];   // W1 fp16, layout [E][D][H]
__device__ __half g_W2h[(size_t)NE * HID * DIM];   // W2 fp16, layout [E][H][D]
__device__ __half g_Hb [(size_t)NE * CAP * HID];   // gelu(x@W1+b1), fp16

// ---------------------------------------------------------------------------
// PTX helpers (baseline compute_103-legal only: cp.async / ldmatrix / mma.sync)
// ---------------------------------------------------------------------------
__device__ __forceinline__ uint32_t smem_u32(const void* p) {
    uint32_t a;
    asm("{ .reg .u64 t; cvta.to.shared.u64 t, %1; cvt.u32.u64 %0, t; }"
        : "=r"(a) : "l"(p));
    return a;
}

__device__ __forceinline__ void cp16(uint32_t smaddr, const void* g) {
    asm volatile("cp.async.cg.shared.global [%0], [%1], 16;"
                 :: "r"(smaddr), "l"(g));
}
#define CP_COMMIT() asm volatile("cp.async.commit_group;" ::: "memory")
#define CP_WAIT(n)  asm volatile("cp.async.wait_group %0;" :: "n"(n) : "memory")

__device__ __forceinline__ void ldsm_x4(uint32_t* r, uint32_t addr) {
    asm volatile("ldmatrix.sync.aligned.m8n8.x4.shared.b16 {%0,%1,%2,%3}, [%4];"
                 : "=r"(r[0]), "=r"(r[1]), "=r"(r[2]), "=r"(r[3]) : "r"(addr));
}
__device__ __forceinline__ void ldsm_x4_t(uint32_t* r, uint32_t addr) {
    asm volatile("ldmatrix.sync.aligned.m8n8.x4.trans.shared.b16 {%0,%1,%2,%3}, [%4];"
                 : "=r"(r[0]), "=r"(r[1]), "=r"(r[2]), "=r"(r[3]) : "r"(addr));
}

__device__ __forceinline__ void mma16816(float* c, const uint32_t* a, const uint32_t* b) {
    asm volatile(
        "mma.sync.aligned.m16n8k16.row.col.f32.f16.f16.f32 "
        "{%0,%1,%2,%3}, {%4,%5,%6,%7}, {%8,%9}, {%0,%1,%2,%3};"
        : "+f"(c[0]), "+f"(c[1]), "+f"(c[2]), "+f"(c[3])
        : "r"(a[0]), "r"(a[1]), "r"(a[2]), "r"(a[3]), "r"(b[0]), "r"(b[1]));
}

// tanh-approximate GELU (JAX default): x * sigmoid(2u), u = 0.79788(x+0.044715x^3)
__device__ __forceinline__ float gelu_f(float v) {
    float u2 = 2.0f * 0.7978845608028654f * (v + 0.044715f * v * v * v);
    u2 = fminf(fmaxf(u2, -30.0f), 30.0f);
    float t = __expf(u2);
    return v * __fdividef(t, t + 1.0f);
}

// ---------------------------------------------------------------------------
// Kernel 1: zero expert counters (must precede router only)
// ---------------------------------------------------------------------------
__global__ void zero_cnt_kernel() {
    if (threadIdx.x < NE) g_cnt[threadIdx.x] = 0;
}

// ---------------------------------------------------------------------------
// Kernel 2: fused router + gather — one warp per token.
// Computes logits -> softmax -> top2, claims slots, then writes the fp16 row
// into both expert buffers while the token row is L1-resident (x read once).
// ---------------------------------------------------------------------------
__global__ void router_gather_kernel(const float* __restrict__ x,
                                     const float* __restrict__ Wr) {
    int gwarp = (blockIdx.x * blockDim.x + threadIdx.x) >> 5;
    int lane = threadIdx.x & 31;
    if (gwarp >= NTOK) return;
    const float* xr = x + (size_t)gwarp * DIM;
    float a0 = 0, a1 = 0, a2 = 0, a3 = 0, a4 = 0, a5 = 0, a6 = 0, a7 = 0;
    for (int d = lane; d < DIM; d += 32) {
        float xv = xr[d];
        const float4* w = (const float4*)(Wr + (size_t)d * NE);
        float4 w0 = w[0], w1 = w[1];
        a0 += xv * w0.x; a1 += xv * w0.y; a2 += xv * w0.z; a3 += xv * w0.w;
        a4 += xv * w1.x; a5 += xv * w1.y; a6 += xv * w1.z; a7 += xv * w1.w;
    }
#pragma unroll
    for (int o = 16; o > 0; o >>= 1) {
        a0 += __shfl_xor_sync(0xffffffffu, a0, o);
        a1 += __shfl_xor_sync(0xffffffffu, a1, o);
        a2 += __shfl_xor_sync(0xffffffffu, a2, o);
        a3 += __shfl_xor_sync(0xffffffffu, a3, o);
        a4 += __shfl_xor_sync(0xffffffffu, a4, o);
        a5 += __shfl_xor_sync(0xffffffffu, a5, o);
        a6 += __shfl_xor_sync(0xffffffffu, a6, o);
        a7 += __shfl_xor_sync(0xffffffffu, a7, o);
    }
    int i1 = 0, i2 = 0, s1 = 0, s2 = 0;
    if (lane == 0) {
        float p[8] = {a0, a1, a2, a3, a4, a5, a6, a7};
        float m = p[0];
#pragma unroll
        for (int e = 1; e < 8; e++) m = fmaxf(m, p[e]);
        float s = 0.f;
#pragma unroll
        for (int e = 0; e < 8; e++) { p[e] = expf(p[e] - m); s += p[e]; }
        float inv = 1.0f / s;
#pragma unroll
        for (int e = 0; e < 8; e++) p[e] *= inv;
        float v1 = p[0]; i1 = 0;
#pragma unroll
        for (int e = 1; e < 8; e++) if (p[e] > v1) { v1 = p[e]; i1 = e; }
        float v2 = -1.0f; i2 = -1;
#pragma unroll
        for (int e = 0; e < 8; e++)
            if (e != i1 && p[e] > v2) { v2 = p[e]; i2 = e; }
        s1 = atomicAdd(&g_cnt[i1], 1);
        g_ptok[i1 * CAP + s1] = gwarp; g_pgate[i1 * CAP + s1] = v1;
        s2 = atomicAdd(&g_cnt[i2], 1);
        g_ptok[i2 * CAP + s2] = gwarp; g_pgate[i2 * CAP + s2] = v2;
    }
    i1 = __shfl_sync(0xffffffffu, i1, 0);
    i2 = __shfl_sync(0xffffffffu, i2, 0);
    s1 = __shfl_sync(0xffffffffu, s1, 0);
    s2 = __shfl_sync(0xffffffffu, s2, 0);

    // gather: convert row to fp16 and scatter into both expert buffers.
    // x row is hot in L1 from the logits pass; half2 stores are coalesced.
    unsigned* d1 = (unsigned*)(g_X + ((size_t)i1 * CAP + s1) * DIM);
    unsigned* d2 = (unsigned*)(g_X + ((size_t)i2 * CAP + s2) * DIM);
    const float2* xf2 = (const float2*)xr;
#pragma unroll
    for (int i = 0; i < 16; i++) {
        int j = lane + i * 32;               // half2 index, 512 per row
        float2 v = __ldg(&xf2[j]);
        __half2 h = __floats2half2_rn(v.x, v.y);
        unsigned u = *reinterpret_cast<unsigned*>(&h);
        d1[j] = u; d2[j] = u;
    }
}

// ---------------------------------------------------------------------------
// Kernel 3: fp32 -> fp16 weight convert + zero `out` (out only needed by GEMM2).
// First ZBLK blocks zero the output; the rest convert W1/W2.
// ---------------------------------------------------------------------------
#define ZBLK 128
__global__ void convert_w_kernel(const float* __restrict__ W1,
                                 const float* __restrict__ W2,
                                 float* __restrict__ out) {
    if (blockIdx.x < ZBLK) {
        size_t n4 = (size_t)NTOK * DIM / 4;
        size_t stride = (size_t)ZBLK * blockDim.x;
        float4 z = make_float4(0.f, 0.f, 0.f, 0.f);
        for (size_t i = (size_t)blockIdx.x * blockDim.x + threadIdx.x; i < n4; i += stride)
            ((float4*)out)[i] = z;
        return;
    }
    int nb = gridDim.x - ZBLK;
    size_t n4 = (size_t)NE * DIM * HID / 4;
    size_t stride = (size_t)nb * blockDim.x;
    for (size_t i = (size_t)(blockIdx.x - ZBLK) * blockDim.x + threadIdx.x; i < n4; i += stride) {
        float4 v1 = ((const float4*)W1)[i];
        float4 v2 = ((const float4*)W2)[i];
        __half2 a0 = __floats2half2_rn(v1.x, v1.y);
        __half2 a1 = __floats2half2_rn(v1.z, v1.w);
        __half2 b0 = __floats2half2_rn(v2.x, v2.y);
        __half2 b1 = __floats2half2_rn(v2.z, v2.w);
        uint2 u1, u2;
        u1.x = *reinterpret_cast<unsigned*>(&a0);
        u1.y = *reinterpret_cast<unsigned*>(&a1);
        u2.x = *reinterpret_cast<unsigned*>(&b0);
        u2.y = *reinterpret_cast<unsigned*>(&b1);
        ((uint2*)g_W1h)[i] = u1;
        ((uint2*)g_W2h)[i] = u2;
    }
}

// ---------------------------------------------------------------------------
// Kernel 4: fp16 mma.sync GEMM, 128x128x32 tiles, 4-stage cp.async pipeline,
// single __syncthreads per K-iteration.  (R4 configuration — measured best.)
// mode 0: H = gelu(X @ W1 + b1)        (A = g_X [rows,D], B = W1h [D,H])
// mode 1: out[tok] += gate*(H @ W2+b2) (A = g_Hb [rows,H], B = W2h [H,D])
// 8 warps as 4(M) x 2(N); warp tile 32x64; mma m16n8k16.
// ---------------------------------------------------------------------------
struct GSmem {
    __half A[ST][BM][LDA];   // 4 * 128*40*2 = 40960 B
    __half B[ST][BK][LDB];   // 4 * 32*136*2 = 34816 B
};
#define GSMEM_BYTES ((int)sizeof(GSmem))   // 75776 B

__global__ void __launch_bounds__(256, 2)
moe_gemm_kernel(int mode, const float* __restrict__ bias, float* __restrict__ out) {
    extern __shared__ char dyn_smem[];
    GSmem& sm = *reinterpret_cast<GSmem*>(dyn_smem);

    int e = blockIdx.z;
    int cnt = g_cnt[e];
    int row0 = blockIdx.y * BM;
    if (row0 >= cnt) return;
    int valid = cnt - row0;          // rows alive in this tile (may exceed BM)
    int nb0 = blockIdx.x * BN;

    const __half* Ag; const __half* Bg;
    int lda, ldb, Kdim;
    if (mode == 0) {
        Ag = g_X   + (size_t)e * CAP * DIM + (size_t)row0 * DIM;  lda = DIM;
        Bg = g_W1h + (size_t)e * DIM * HID;                       ldb = HID;
        Kdim = DIM;
    } else {
        Ag = g_Hb  + (size_t)e * CAP * HID + (size_t)row0 * HID;  lda = HID;
        Bg = g_W2h + (size_t)e * HID * DIM;                       ldb = DIM;
        Kdim = HID;
    }

    int tid = threadIdx.x;
    int lane = tid & 31;
    int warp = tid >> 5;
    int wm = warp >> 1;              // 0..3  (M groups of 32)
    int wn = warp & 1;               // 0..1  (N groups of 64)

    float acc[2][8][4];
#pragma unroll
    for (int mi = 0; mi < 2; mi++)
#pragma unroll
        for (int nj = 0; nj < 8; nj++)
#pragma unroll
            for (int q = 0; q < 4; q++) acc[mi][nj][q] = 0.f;

    // --- cp.async stage loader: A tile 128x32 (512 x 16B), B tile 32x128 (512 x 16B)
    auto load_stage = [&](int kt, int s) {
#pragma unroll
        for (int i = 0; i < 2; i++) {
            int c = tid + i * 256;
            int r = c >> 2, cc = c & 3;
            cp16(smem_u32(&sm.A[s][r][cc * 8]),
                 Ag + (size_t)r * lda + kt * BK + cc * 8);
        }
#pragma unroll
        for (int i = 0; i < 2; i++) {
            int c = tid + i * 256;
            int r = c >> 4, cc = c & 15;
            cp16(smem_u32(&sm.B[s][r][cc * 8]),
                 Bg + (size_t)(kt * BK + r) * ldb + nb0 + cc * 8);
        }
        CP_COMMIT();
    };

    int nk = Kdim / BK;              // 32 (GEMM1) or 128 (GEMM2); always > ST
    // prologue: fill ST-1 stages (3 groups in flight)
#pragma unroll
    for (int p = 0; p < ST - 1; p++) load_stage(p, p);

    for (int kt = 0; kt < nk; kt++) {
        CP_WAIT(ST - 2);             // <=2 groups pending -> stage kt resident
        __syncthreads();             // also proves stage (kt-1) fully consumed
        if (kt + ST - 1 < nk) load_stage(kt + ST - 1, (kt + ST - 1) % ST);
        else                  CP_COMMIT();   // empty group keeps wait invariant
        int cur = kt % ST;

#pragma unroll
        for (int ks = 0; ks < 2; ks++) {
            uint32_t af[2][4];
#pragma unroll
            for (int mi = 0; mi < 2; mi++) {
                int r = wm * 32 + mi * 16 + (lane & 15);
                int cc = ks * 16 + ((lane >> 4) << 3);
                ldsm_x4(af[mi], smem_u32(&sm.A[cur][r][cc]));
            }
            uint32_t bf[8][2];
#pragma unroll
            for (int j = 0; j < 4; j++) {
                int kr = ks * 16 + (lane & 7) + (((lane >> 3) & 1) << 3);
                int nc = wn * 64 + j * 16 + ((lane >> 4) << 3);
                uint32_t r4[4];
                ldsm_x4_t(r4, smem_u32(&sm.B[cur][kr][nc]));
                bf[2 * j][0] = r4[0]; bf[2 * j][1] = r4[1];
                bf[2 * j + 1][0] = r4[2]; bf[2 * j + 1][1] = r4[3];
            }
#pragma unroll
            for (int mi = 0; mi < 2; mi++)
#pragma unroll
                for (int nj = 0; nj < 8; nj++)
                    mma16816(acc[mi][nj], af[mi], bf[nj]);
        }
    }

    // --- Epilogue. acc[mi][nj]: rows wm*32+mi*16+{lane/4, +8}, cols wn*64+nj*8+(lane%4)*2+{0,1}
    if (mode == 0) {
        const float* bp = bias + (size_t)e * HID + nb0;
#pragma unroll
        for (int mi = 0; mi < 2; mi++) {
            int rb = wm * 32 + mi * 16 + (lane >> 2);
#pragma unroll
            for (int hr = 0; hr < 2; hr++) {
                int r = rb + hr * 8;
                if (r < valid) {
                    size_t rowoff = ((size_t)e * CAP + row0 + r) * HID + nb0;
#pragma unroll
                    for (int nj = 0; nj < 8; nj++) {
                        int colc = wn * 64 + nj * 8 + ((lane & 3) << 1);
                        float v0 = acc[mi][nj][hr * 2 + 0] + bp[colc];
                        float v1 = acc[mi][nj][hr * 2 + 1] + bp[colc + 1];
                        __half2 h2 = __floats2half2_rn(gelu_f(v0), gelu_f(v1));
                        *(__half2*)(g_Hb + rowoff + colc) = h2;
                    }
                }
            }
        }
    } else {
        const float* bp = bias + (size_t)e * DIM + nb0;
#pragma unroll
        for (int mi = 0; mi < 2; mi++) {
            int rb = wm * 32 + mi * 16 + (lane >> 2);
#pragma unroll
            for (int hr = 0; hr < 2; hr++) {
                int r = rb + hr * 8;
                if (r < valid) {
                    int t = g_ptok[e * CAP + row0 + r];
                    float gate = g_pgate[e * CAP + row0 + r];
                    float* orow = out + (size_t)t * DIM + nb0;
#pragma unroll
                    for (int nj = 0; nj < 8; nj++) {
                        int colc = wn * 64 + nj * 8 + ((lane & 3) << 1);
                        float v0 = acc[mi][nj][hr * 2 + 0] + bp[colc];
                        float v1 = acc[mi][nj][hr * 2 + 1] + bp[colc + 1];
                        atomicAdd(orow + colc,     gate * v0);
                        atomicAdd(orow + colc + 1, gate * v1);
                    }
                }
            }
        }
    }
}

// ---------------------------------------------------------------------------
// Launch
// ---------------------------------------------------------------------------
extern "C" void kernel_launch(void* const* d_in, const int* in_sizes, int n_in,
                              void* d_out, int out_size) {
    const float* x  = (const float*)d_in[0];
    const float* Wr = (const float*)d_in[1];
    const float* W1 = (const float*)d_in[2];
    const float* b1 = (const float*)d_in[3];
    const float* W2 = (const float*)d_in[4];
    const float* b2 = (const float*)d_in[5];
    float* out = (float*)d_out;

    static int smem_set = 0;
    if (!smem_set) {
        cudaFuncSetAttribute(moe_gemm_kernel,
                             cudaFuncAttributeMaxDynamicSharedMemorySize,
                             GSMEM_BYTES);
        smem_set = 1;
    }

    // 1. zero expert counters (router dependency only)
    zero_cnt_kernel<<<1, 32>>>();
    // 2. fused router + gather (reads x once)
    router_gather_kernel<<<NTOK / 8, 256>>>(x, Wr);
    // 3. weight fp32->fp16 convert + zero `out`
    convert_w_kernel<<<2048 + ZBLK, 256>>>(W1, W2, out);
    // 4. GEMM1: H = gelu(X @ W1 + b1)
    moe_gemm_kernel<<<dim3(HID / BN, CAP / BM, NE), 256, GSMEM_BYTES>>>(0, b1, nullptr);
    // 5. GEMM2: out += gate * (H @ W2 + b2)
    moe_gemm_kernel<<<dim3(DIM / BN, CAP / BM, NE), 256, GSMEM_BYTES>>>(1, b2, out);
}

// round 7
// speedup vs baseline: 1.4273x; 1.1130x over previous
#include <cuda_runtime.h>
#include <cuda_fp16.h>
#include <cstdint>

// ---------------------------------------------------------------------------
// Problem dims (fixed by the dataset)
// ---------------------------------------------------------------------------
#define NTOK 8192          // B*S tokens
#define DIM  1024          // model dim
#define HID  4096          // hidden dim
#define NE   8             // experts
#define CAP  8192          // per-expert token capacity (max possible)

#define BM 128
#define BN 128
#define BK 32
#define ST 4               // cp.async pipeline stages
#define LDA (BK + 8)       // 40 halves  (80B rows, conflict-free for ldmatrix)
#define LDB (BN + 8)       // 136 halves (272B rows, conflict-free for ldmatrix)
#define ASTAGE (BM * LDA * 2)      // 10240 B per A stage
#define BSTAGE (BK * LDB * 2)      // 8704 B per B stage

// ---------------------------------------------------------------------------
// Scratch (static __device__ arrays; allocation-free kernel_launch)
// ---------------------------------------------------------------------------
__device__ int    g_cnt[NE];
__device__ int    g_ptok[NE * CAP];
__device__ float  g_pgate[NE * CAP];
__device__ __half g_X  [(size_t)NE * CAP * DIM];   // gathered tokens, fp16
__device__ __half g_W1h[(size_t)NE * DIM * HID];   // W1 fp16, layout [E][D][H]
__device__ __half g_W2h[(size_t)NE * HID * DIM];   // W2 fp16, layout [E][H][D]
__device__ __half g_Hb [(size_t)NE * CAP * HID];   // gelu(x@W1+b1), fp16

// ---------------------------------------------------------------------------
// PTX helpers (baseline compute_103-legal only: cp.async / ldmatrix / mma.sync)
// ---------------------------------------------------------------------------
__device__ __forceinline__ uint32_t smem_u32(const void* p) {
    uint32_t a;
    asm("{ .reg .u64 t; cvta.to.shared.u64 t, %1; cvt.u32.u64 %0, t; }"
        : "=r"(a) : "l"(p));
    return a;
}

__device__ __forceinline__ void cp16(uint32_t smaddr, const void* g) {
    asm volatile("cp.async.cg.shared.global [%0], [%1], 16;"
                 :: "r"(smaddr), "l"(g));
}
#define CP_COMMIT() asm volatile("cp.async.commit_group;" ::: "memory")
#define CP_WAIT(n)  asm volatile("cp.async.wait_group %0;" :: "n"(n) : "memory")

__device__ __forceinline__ void ldsm_x4(uint32_t* r, uint32_t addr) {
    asm volatile("ldmatrix.sync.aligned.m8n8.x4.shared.b16 {%0,%1,%2,%3}, [%4];"
                 : "=r"(r[0]), "=r"(r[1]), "=r"(r[2]), "=r"(r[3]) : "r"(addr));
}
__device__ __forceinline__ void ldsm_x4_t(uint32_t* r, uint32_t addr) {
    asm volatile("ldmatrix.sync.aligned.m8n8.x4.trans.shared.b16 {%0,%1,%2,%3}, [%4];"
                 : "=r"(r[0]), "=r"(r[1]), "=r"(r[2]), "=r"(r[3]) : "r"(addr));
}

__device__ __forceinline__ void mma16816(float* c, const uint32_t* a, const uint32_t* b) {
    asm volatile(
        "mma.sync.aligned.m16n8k16.row.col.f32.f16.f16.f32 "
        "{%0,%1,%2,%3}, {%4,%5,%6,%7}, {%8,%9}, {%0,%1,%2,%3};"
        : "+f"(c[0]), "+f"(c[1]), "+f"(c[2]), "+f"(c[3])
        : "r"(a[0]), "r"(a[1]), "r"(a[2]), "r"(a[3]), "r"(b[0]), "r"(b[1]));
}

// tanh-approximate GELU (JAX default): x * sigmoid(2u), u = 0.79788(x+0.044715x^3)
__device__ __forceinline__ float gelu_f(float v) {
    float u2 = 2.0f * 0.7978845608028654f * (v + 0.044715f * v * v * v);
    u2 = fminf(fmaxf(u2, -30.0f), 30.0f);
    float t = __expf(u2);
    return v * __fdividef(t, t + 1.0f);
}

// ---------------------------------------------------------------------------
// Kernel 1: zero expert counters (must precede router only)
// ---------------------------------------------------------------------------
__global__ void zero_cnt_kernel() {
    if (threadIdx.x < NE) g_cnt[threadIdx.x] = 0;
}

// ---------------------------------------------------------------------------
// Kernel 2: fused router + gather — one warp per token.
// ---------------------------------------------------------------------------
__global__ void router_gather_kernel(const float* __restrict__ x,
                                     const float* __restrict__ Wr) {
    int gwarp = (blockIdx.x * blockDim.x + threadIdx.x) >> 5;
    int lane = threadIdx.x & 31;
    if (gwarp >= NTOK) return;
    const float* xr = x + (size_t)gwarp * DIM;
    float a0 = 0, a1 = 0, a2 = 0, a3 = 0, a4 = 0, a5 = 0, a6 = 0, a7 = 0;
    for (int d = lane; d < DIM; d += 32) {
        float xv = xr[d];
        const float4* w = (const float4*)(Wr + (size_t)d * NE);
        float4 w0 = w[0], w1 = w[1];
        a0 += xv * w0.x; a1 += xv * w0.y; a2 += xv * w0.z; a3 += xv * w0.w;
        a4 += xv * w1.x; a5 += xv * w1.y; a6 += xv * w1.z; a7 += xv * w1.w;
    }
#pragma unroll
    for (int o = 16; o > 0; o >>= 1) {
        a0 += __shfl_xor_sync(0xffffffffu, a0, o);
        a1 += __shfl_xor_sync(0xffffffffu, a1, o);
        a2 += __shfl_xor_sync(0xffffffffu, a2, o);
        a3 += __shfl_xor_sync(0xffffffffu, a3, o);
        a4 += __shfl_xor_sync(0xffffffffu, a4, o);
        a5 += __shfl_xor_sync(0xffffffffu, a5, o);
        a6 += __shfl_xor_sync(0xffffffffu, a6, o);
        a7 += __shfl_xor_sync(0xffffffffu, a7, o);
    }
    int i1 = 0, i2 = 0, s1 = 0, s2 = 0;
    if (lane == 0) {
        float p[8] = {a0, a1, a2, a3, a4, a5, a6, a7};
        float m = p[0];
#pragma unroll
        for (int e = 1; e < 8; e++) m = fmaxf(m, p[e]);
        float s = 0.f;
#pragma unroll
        for (int e = 0; e < 8; e++) { p[e] = expf(p[e] - m); s += p[e]; }
        float inv = 1.0f / s;
#pragma unroll
        for (int e = 0; e < 8; e++) p[e] *= inv;
        float v1 = p[0]; i1 = 0;
#pragma unroll
        for (int e = 1; e < 8; e++) if (p[e] > v1) { v1 = p[e]; i1 = e; }
        float v2 = -1.0f; i2 = -1;
#pragma unroll
        for (int e = 0; e < 8; e++)
            if (e != i1 && p[e] > v2) { v2 = p[e]; i2 = e; }
        s1 = atomicAdd(&g_cnt[i1], 1);
        g_ptok[i1 * CAP + s1] = gwarp; g_pgate[i1 * CAP + s1] = v1;
        s2 = atomicAdd(&g_cnt[i2], 1);
        g_ptok[i2 * CAP + s2] = gwarp; g_pgate[i2 * CAP + s2] = v2;
    }
    i1 = __shfl_sync(0xffffffffu, i1, 0);
    i2 = __shfl_sync(0xffffffffu, i2, 0);
    s1 = __shfl_sync(0xffffffffu, s1, 0);
    s2 = __shfl_sync(0xffffffffu, s2, 0);

    unsigned* d1 = (unsigned*)(g_X + ((size_t)i1 * CAP + s1) * DIM);
    unsigned* d2 = (unsigned*)(g_X + ((size_t)i2 * CAP + s2) * DIM);
    const float2* xf2 = (const float2*)xr;
#pragma unroll
    for (int i = 0; i < 16; i++) {
        int j = lane + i * 32;               // half2 index, 512 per row
        float2 v = __ldg(&xf2[j]);
        __half2 h = __floats2half2_rn(v.x, v.y);
        unsigned u = *reinterpret_cast<unsigned*>(&h);
        d1[j] = u; d2[j] = u;
    }
}

// ---------------------------------------------------------------------------
// Kernel 3: fp32 -> fp16 weight convert + zero `out`.
// ---------------------------------------------------------------------------
#define ZBLK 128
__global__ void convert_w_kernel(const float* __restrict__ W1,
                                 const float* __restrict__ W2,
                                 float* __restrict__ out) {
    if (blockIdx.x < ZBLK) {
        size_t n4 = (size_t)NTOK * DIM / 4;
        size_t stride = (size_t)ZBLK * blockDim.x;
        float4 z = make_float4(0.f, 0.f, 0.f, 0.f);
        for (size_t i = (size_t)blockIdx.x * blockDim.x + threadIdx.x; i < n4; i += stride)
            ((float4*)out)[i] = z;
        return;
    }
    int nb = gridDim.x - ZBLK;
    size_t n4 = (size_t)NE * DIM * HID / 4;
    size_t stride = (size_t)nb * blockDim.x;
    for (size_t i = (size_t)(blockIdx.x - ZBLK) * blockDim.x + threadIdx.x; i < n4; i += stride) {
        float4 v1 = ((const float4*)W1)[i];
        float4 v2 = ((const float4*)W2)[i];
        __half2 a0 = __floats2half2_rn(v1.x, v1.y);
        __half2 a1 = __floats2half2_rn(v1.z, v1.w);
        __half2 b0 = __floats2half2_rn(v2.x, v2.y);
        __half2 b1 = __floats2half2_rn(v2.z, v2.w);
        uint2 u1, u2;
        u1.x = *reinterpret_cast<unsigned*>(&a0);
        u1.y = *reinterpret_cast<unsigned*>(&a1);
        u2.x = *reinterpret_cast<unsigned*>(&b0);
        u2.y = *reinterpret_cast<unsigned*>(&b1);
        ((uint2*)g_W1h)[i] = u1;
        ((uint2*)g_W2h)[i] = u2;
    }
}

// ---------------------------------------------------------------------------
// Kernel 4: fp16 mma.sync GEMM, 128x128x32 tiles, 4-stage cp.async pipeline.
// Mainloop addressing fully hoisted: ldmatrix srcs = 6 base regs + stage
// offset; cp.async dsts = 4 base regs + stage offset; global srcs = advancing
// pointers. One IADD per address in the hot loop.
// ---------------------------------------------------------------------------
struct GSmem {
    __half A[ST][BM][LDA];   // 4 * 10240 B
    __half B[ST][BK][LDB];   // 4 *  8704 B
};
#define GSMEM_BYTES ((int)sizeof(GSmem))   // 75776 B

__global__ void __launch_bounds__(256, 2)
moe_gemm_kernel(int mode, const float* __restrict__ bias, float* __restrict__ out) {
    extern __shared__ char dyn_smem[];

    int e = blockIdx.z;
    int cnt = g_cnt[e];
    int row0 = blockIdx.y * BM;
    if (row0 >= cnt) return;
    int valid = cnt - row0;
    int nb0 = blockIdx.x * BN;

    const __half* Ag; const __half* Bg;
    int lda, ldb, Kdim;
    if (mode == 0) {
        Ag = g_X   + (size_t)e * CAP * DIM + (size_t)row0 * DIM;  lda = DIM;
        Bg = g_W1h + (size_t)e * DIM * HID;                       ldb = HID;
        Kdim = DIM;
    } else {
        Ag = g_Hb  + (size_t)e * CAP * HID + (size_t)row0 * HID;  lda = HID;
        Bg = g_W2h + (size_t)e * HID * DIM;                       ldb = DIM;
        Kdim = HID;
    }

    int tid = threadIdx.x;
    int lane = tid & 31;
    int warp = tid >> 5;
    int wm = warp >> 1;              // 0..3  (M groups of 32)
    int wn = warp & 1;               // 0..1  (N groups of 64)

    // ---- hoisted smem base addresses (all stage-0; add stage offset later)
    uint32_t smemA = smem_u32(dyn_smem);
    uint32_t smemB = smemA + ST * ASTAGE;

    // ldmatrix sources
    uint32_t aaddr0 = smemA + (uint32_t)(((wm * 32 + (lane & 15)) * LDA + ((lane >> 4) << 3)) * 2);
    uint32_t aaddr1 = aaddr0 + 16 * LDA * 2;
    uint32_t bbase  = smemB + (uint32_t)(((lane & 15) * LDB + wn * 64 + ((lane >> 4) << 3)) * 2);
    // j stride = 16 halves = 32 B (compile-time immediates below)

    // cp.async destinations (2 A vectors + 2 B vectors per thread)
    int ca0 = tid,       ca1 = tid + 256;
    uint32_t adst0 = smemA + (uint32_t)(((ca0 >> 2) * LDA + (ca0 & 3) * 8) * 2);
    uint32_t adst1 = smemA + (uint32_t)(((ca1 >> 2) * LDA + (ca1 & 3) * 8) * 2);
    uint32_t bdst0 = smemB + (uint32_t)(((ca0 >> 4) * LDB + (ca0 & 15) * 8) * 2);
    uint32_t bdst1 = smemB + (uint32_t)(((ca1 >> 4) * LDB + (ca1 & 15) * 8) * 2);

    // advancing global source pointers
    const __half* asrc0 = Ag + (size_t)(ca0 >> 2) * lda + (ca0 & 3) * 8;
    const __half* asrc1 = Ag + (size_t)(ca1 >> 2) * lda + (ca1 & 3) * 8;
    const __half* bsrc0 = Bg + (size_t)(ca0 >> 4) * ldb + nb0 + (ca0 & 15) * 8;
    const __half* bsrc1 = Bg + (size_t)(ca1 >> 4) * ldb + nb0 + (ca1 & 15) * 8;
    const size_t bstep = (size_t)BK * ldb;

    float acc[2][8][4];
#pragma unroll
    for (int mi = 0; mi < 2; mi++)
#pragma unroll
        for (int nj = 0; nj < 8; nj++)
#pragma unroll
            for (int q = 0; q < 4; q++) acc[mi][nj][q] = 0.f;

    auto load_stage = [&](uint32_t soff) {
        cp16(adst0 + soff, asrc0);
        cp16(adst1 + soff, asrc1);
        uint32_t bo = soff;                    // scale A-stage offset to B-stage
        bo = (soff / ASTAGE) * BSTAGE;
        cp16(bdst0 + bo, bsrc0);
        cp16(bdst1 + bo, bsrc1);
        CP_COMMIT();
        asrc0 += BK; asrc1 += BK;
        bsrc0 += bstep; bsrc1 += bstep;
    };

    int nk = Kdim / BK;
#pragma unroll
    for (int p = 0; p < ST - 1; p++) load_stage(p * ASTAGE);

    uint32_t cons = 0;                         // consumer A-stage offset
    uint32_t prod = (ST - 1) * ASTAGE;         // producer A-stage offset
    for (int kt = 0; kt < nk; kt++) {
        CP_WAIT(ST - 2);
        __syncthreads();
        if (kt + ST - 1 < nk) {
            load_stage(prod);
            prod += ASTAGE; if (prod == ST * ASTAGE) prod = 0;
        } else CP_COMMIT();

        uint32_t aA = aaddr0 + cons, aB = aaddr1 + cons;
        uint32_t bA = bbase + (cons / ASTAGE) * BSTAGE;

#pragma unroll
        for (int ks = 0; ks < 2; ks++) {
            const uint32_t ksa = ks * 32;              // 16 halves
            const uint32_t ksb = ks * 16 * LDB * 2;    // 16 rows
            uint32_t af[2][4];
            ldsm_x4(af[0], aA + ksa);
            ldsm_x4(af[1], aB + ksa);
            uint32_t bf[8][2];
#pragma unroll
            for (int j = 0; j < 4; j++) {
                uint32_t r4[4];
                ldsm_x4_t(r4, bA + ksb + j * 32);
                bf[2 * j][0] = r4[0]; bf[2 * j][1] = r4[1];
                bf[2 * j + 1][0] = r4[2]; bf[2 * j + 1][1] = r4[3];
            }
#pragma unroll
            for (int mi = 0; mi < 2; mi++)
#pragma unroll
                for (int nj = 0; nj < 8; nj++)
                    mma16816(acc[mi][nj], af[mi], bf[nj]);
        }
        cons += ASTAGE; if (cons == ST * ASTAGE) cons = 0;
    }

    // --- Epilogue. acc[mi][nj]: rows wm*32+mi*16+{lane/4,+8}, cols wn*64+nj*8+(lane%4)*2+{0,1}
    if (mode == 0) {
        const float* bp = bias + (size_t)e * HID + nb0;
#pragma unroll
        for (int mi = 0; mi < 2; mi++) {
            int rb = wm * 32 + mi * 16 + (lane >> 2);
#pragma unroll
            for (int hr = 0; hr < 2; hr++) {
                int r = rb + hr * 8;
                if (r < valid) {
                    size_t rowoff = ((size_t)e * CAP + row0 + r) * HID + nb0;
#pragma unroll
                    for (int nj = 0; nj < 8; nj++) {
                        int colc = wn * 64 + nj * 8 + ((lane & 3) << 1);
                        float v0 = acc[mi][nj][hr * 2 + 0] + bp[colc];
                        float v1 = acc[mi][nj][hr * 2 + 1] + bp[colc + 1];
                        __half2 h2 = __floats2half2_rn(gelu_f(v0), gelu_f(v1));
                        *(__half2*)(g_Hb + rowoff + colc) = h2;
                    }
                }
            }
        }
    } else {
        const float* bp = bias + (size_t)e * DIM + nb0;
#pragma unroll
        for (int mi = 0; mi < 2; mi++) {
            int rb = wm * 32 + mi * 16 + (lane >> 2);
#pragma unroll
            for (int hr = 0; hr < 2; hr++) {
                int r = rb + hr * 8;
                if (r < valid) {
                    int t = g_ptok[e * CAP + row0 + r];
                    float gate = g_pgate[e * CAP + row0 + r];
                    float* orow = out + (size_t)t * DIM + nb0;
#pragma unroll
                    for (int nj = 0; nj < 8; nj++) {
                        int colc = wn * 64 + nj * 8 + ((lane & 3) << 1);
                        float v0 = acc[mi][nj][hr * 2 + 0] + bp[colc];
                        float v1 = acc[mi][nj][hr * 2 + 1] + bp[colc + 1];
                        atomicAdd(orow + colc,     gate * v0);
                        atomicAdd(orow + colc + 1, gate * v1);
                    }
                }
            }
        }
    }
}

// ---------------------------------------------------------------------------
// Launch
// ---------------------------------------------------------------------------
extern "C" void kernel_launch(void* const* d_in, const int* in_sizes, int n_in,
                              void* d_out, int out_size) {
    const float* x  = (const float*)d_in[0];
    const float* Wr = (const float*)d_in[1];
    const float* W1 = (const float*)d_in[2];
    const float* b1 = (const float*)d_in[3];
    const float* W2 = (const float*)d_in[4];
    const float* b2 = (const float*)d_in[5];
    float* out = (float*)d_out;

    static int smem_set = 0;
    if (!smem_set) {
        cudaFuncSetAttribute(moe_gemm_kernel,
                             cudaFuncAttributeMaxDynamicSharedMemorySize,
                             GSMEM_BYTES);
        smem_set = 1;
    }

    zero_cnt_kernel<<<1, 32>>>();
    router_gather_kernel<<<NTOK / 8, 256>>>(x, Wr);
    convert_w_kernel<<<2048 + ZBLK, 256>>>(W1, W2, out);
    moe_gemm_kernel<<<dim3(HID / BN, CAP / BM, NE), 256, GSMEM_BYTES>>>(0, b1, nullptr);
    moe_gemm_kernel<<<dim3(DIM / BN, CAP / BM, NE), 256, GSMEM_BYTES>>>(1, b2, out);
}

// round 8
// speedup vs baseline: 1.4958x; 1.0480x over previous
#include <cuda_runtime.h>
#include <cuda_fp16.h>
#include <cstdint>

// ---------------------------------------------------------------------------
// Problem dims (fixed by the dataset)
// ---------------------------------------------------------------------------
#define NTOK 8192          // B*S tokens
#define DIM  1024          // model dim
#define HID  4096          // hidden dim
#define NE   8             // experts
#define CAP  8192          // per-expert token capacity (max possible)

#define BM 128
#define BN 128
#define BK 64
#define LDA (BK + 8)       // 72 halves (144B rows; bank stride 4 -> conflict-free)
#define LDB (BN + 8)       // 136 halves (272B rows; conflict-free for ldmatrix)
#define ASTAGE (BM * LDA * 2)      // 18432 B per A stage
#define BSTAGE (BK * LDB * 2)      // 17408 B per B stage
// 2 stages: (18432+17408)*2 = 71680 B per CTA -> 2 CTAs/SM

// ---------------------------------------------------------------------------
// Scratch (static __device__ arrays; allocation-free kernel_launch)
// ---------------------------------------------------------------------------
__device__ int    g_cnt[NE];
__device__ int    g_ptok[NE * CAP];
__device__ float  g_pgate[NE * CAP];
__device__ __half g_X  [(size_t)NE * CAP * DIM];   // gathered tokens, fp16
__device__ __half g_W1h[(size_t)NE * DIM * HID];   // W1 fp16, layout [E][D][H]
__device__ __half g_W2h[(size_t)NE * HID * DIM];   // W2 fp16, layout [E][H][D]
__device__ __half g_Hb [(size_t)NE * CAP * HID];   // gelu(x@W1+b1), fp16

// ---------------------------------------------------------------------------
// PTX helpers (baseline compute_103-legal only: cp.async / ldmatrix / mma.sync)
// ---------------------------------------------------------------------------
__device__ __forceinline__ uint32_t smem_u32(const void* p) {
    uint32_t a;
    asm("{ .reg .u64 t; cvta.to.shared.u64 t, %1; cvt.u32.u64 %0, t; }"
        : "=r"(a) : "l"(p));
    return a;
}

__device__ __forceinline__ void cp16(uint32_t smaddr, const void* g) {
    asm volatile("cp.async.cg.shared.global [%0], [%1], 16;"
                 :: "r"(smaddr), "l"(g));
}
#define CP_COMMIT() asm volatile("cp.async.commit_group;" ::: "memory")
#define CP_WAIT(n)  asm volatile("cp.async.wait_group %0;" :: "n"(n) : "memory")

__device__ __forceinline__ void ldsm_x4(uint32_t* r, uint32_t addr) {
    asm volatile("ldmatrix.sync.aligned.m8n8.x4.shared.b16 {%0,%1,%2,%3}, [%4];"
                 : "=r"(r[0]), "=r"(r[1]), "=r"(r[2]), "=r"(r[3]) : "r"(addr));
}
__device__ __forceinline__ void ldsm_x4_t(uint32_t* r, uint32_t addr) {
    asm volatile("ldmatrix.sync.aligned.m8n8.x4.trans.shared.b16 {%0,%1,%2,%3}, [%4];"
                 : "=r"(r[0]), "=r"(r[1]), "=r"(r[2]), "=r"(r[3]) : "r"(addr));
}

__device__ __forceinline__ void mma16816(float* c, const uint32_t* a, const uint32_t* b) {
    asm volatile(
        "mma.sync.aligned.m16n8k16.row.col.f32.f16.f16.f32 "
        "{%0,%1,%2,%3}, {%4,%5,%6,%7}, {%8,%9}, {%0,%1,%2,%3};"
        : "+f"(c[0]), "+f"(c[1]), "+f"(c[2]), "+f"(c[3])
        : "r"(a[0]), "r"(a[1]), "r"(a[2]), "r"(a[3]), "r"(b[0]), "r"(b[1]));
}

// tanh-approximate GELU (JAX default): x * sigmoid(2u), u = 0.79788(x+0.044715x^3)
__device__ __forceinline__ float gelu_f(float v) {
    float u2 = 2.0f * 0.7978845608028654f * (v + 0.044715f * v * v * v);
    u2 = fminf(fmaxf(u2, -30.0f), 30.0f);
    float t = __expf(u2);
    return v * __fdividef(t, t + 1.0f);
}

// ---------------------------------------------------------------------------
// Kernel 1: zero expert counters (must precede router only)
// ---------------------------------------------------------------------------
__global__ void zero_cnt_kernel() {
    if (threadIdx.x < NE) g_cnt[threadIdx.x] = 0;
}

// ---------------------------------------------------------------------------
// Kernel 2: fused router + gather — one warp per token.
// ---------------------------------------------------------------------------
__global__ void router_gather_kernel(const float* __restrict__ x,
                                     const float* __restrict__ Wr) {
    int gwarp = (blockIdx.x * blockDim.x + threadIdx.x) >> 5;
    int lane = threadIdx.x & 31;
    if (gwarp >= NTOK) return;
    const float* xr = x + (size_t)gwarp * DIM;
    float a0 = 0, a1 = 0, a2 = 0, a3 = 0, a4 = 0, a5 = 0, a6 = 0, a7 = 0;
    for (int d = lane; d < DIM; d += 32) {
        float xv = xr[d];
        const float4* w = (const float4*)(Wr + (size_t)d * NE);
        float4 w0 = w[0], w1 = w[1];
        a0 += xv * w0.x; a1 += xv * w0.y; a2 += xv * w0.z; a3 += xv * w0.w;
        a4 += xv * w1.x; a5 += xv * w1.y; a6 += xv * w1.z; a7 += xv * w1.w;
    }
#pragma unroll
    for (int o = 16; o > 0; o >>= 1) {
        a0 += __shfl_xor_sync(0xffffffffu, a0, o);
        a1 += __shfl_xor_sync(0xffffffffu, a1, o);
        a2 += __shfl_xor_sync(0xffffffffu, a2, o);
        a3 += __shfl_xor_sync(0xffffffffu, a3, o);
        a4 += __shfl_xor_sync(0xffffffffu, a4, o);
        a5 += __shfl_xor_sync(0xffffffffu, a5, o);
        a6 += __shfl_xor_sync(0xffffffffu, a6, o);
        a7 += __shfl_xor_sync(0xffffffffu, a7, o);
    }
    int i1 = 0, i2 = 0, s1 = 0, s2 = 0;
    if (lane == 0) {
        float p[8] = {a0, a1, a2, a3, a4, a5, a6, a7};
        float m = p[0];
#pragma unroll
        for (int e = 1; e < 8; e++) m = fmaxf(m, p[e]);
        float s = 0.f;
#pragma unroll
        for (int e = 0; e < 8; e++) { p[e] = expf(p[e] - m); s += p[e]; }
        float inv = 1.0f / s;
#pragma unroll
        for (int e = 0; e < 8; e++) p[e] *= inv;
        float v1 = p[0]; i1 = 0;
#pragma unroll
        for (int e = 1; e < 8; e++) if (p[e] > v1) { v1 = p[e]; i1 = e; }
        float v2 = -1.0f; i2 = -1;
#pragma unroll
        for (int e = 0; e < 8; e++)
            if (e != i1 && p[e] > v2) { v2 = p[e]; i2 = e; }
        s1 = atomicAdd(&g_cnt[i1], 1);
        g_ptok[i1 * CAP + s1] = gwarp; g_pgate[i1 * CAP + s1] = v1;
        s2 = atomicAdd(&g_cnt[i2], 1);
        g_ptok[i2 * CAP + s2] = gwarp; g_pgate[i2 * CAP + s2] = v2;
    }
    i1 = __shfl_sync(0xffffffffu, i1, 0);
    i2 = __shfl_sync(0xffffffffu, i2, 0);
    s1 = __shfl_sync(0xffffffffu, s1, 0);
    s2 = __shfl_sync(0xffffffffu, s2, 0);

    unsigned* d1 = (unsigned*)(g_X + ((size_t)i1 * CAP + s1) * DIM);
    unsigned* d2 = (unsigned*)(g_X + ((size_t)i2 * CAP + s2) * DIM);
    const float2* xf2 = (const float2*)xr;
#pragma unroll
    for (int i = 0; i < 16; i++) {
        int j = lane + i * 32;               // half2 index, 512 per row
        float2 v = __ldg(&xf2[j]);
        __half2 h = __floats2half2_rn(v.x, v.y);
        unsigned u = *reinterpret_cast<unsigned*>(&h);
        d1[j] = u; d2[j] = u;
    }
}

// ---------------------------------------------------------------------------
// Kernel 3: fp32 -> fp16 weight convert + zero `out`.
// ---------------------------------------------------------------------------
#define ZBLK 128
__global__ void convert_w_kernel(const float* __restrict__ W1,
                                 const float* __restrict__ W2,
                                 float* __restrict__ out) {
    if (blockIdx.x < ZBLK) {
        size_t n4 = (size_t)NTOK * DIM / 4;
        size_t stride = (size_t)ZBLK * blockDim.x;
        float4 z = make_float4(0.f, 0.f, 0.f, 0.f);
        for (size_t i = (size_t)blockIdx.x * blockDim.x + threadIdx.x; i < n4; i += stride)
            ((float4*)out)[i] = z;
        return;
    }
    int nb = gridDim.x - ZBLK;
    size_t n4 = (size_t)NE * DIM * HID / 4;
    size_t stride = (size_t)nb * blockDim.x;
    for (size_t i = (size_t)(blockIdx.x - ZBLK) * blockDim.x + threadIdx.x; i < n4; i += stride) {
        float4 v1 = ((const float4*)W1)[i];
        float4 v2 = ((const float4*)W2)[i];
        __half2 a0 = __floats2half2_rn(v1.x, v1.y);
        __half2 a1 = __floats2half2_rn(v1.z, v1.w);
        __half2 b0 = __floats2half2_rn(v2.x, v2.y);
        __half2 b1 = __floats2half2_rn(v2.z, v2.w);
        uint2 u1, u2;
        u1.x = *reinterpret_cast<unsigned*>(&a0);
        u1.y = *reinterpret_cast<unsigned*>(&a1);
        u2.x = *reinterpret_cast<unsigned*>(&b0);
        u2.y = *reinterpret_cast<unsigned*>(&b1);
        ((uint2*)g_W1h)[i] = u1;
        ((uint2*)g_W2h)[i] = u2;
    }
}

// ---------------------------------------------------------------------------
// Kernel 4: fp16 mma.sync GEMM, 128x128x64 tiles, 2-stage double buffer.
// One __syncthreads + one cp.async group per 64 K-elements; 4 ks sub-steps
// (64 HMMA) between barriers. All addressing hoisted to base regs + XOR toggle.
// mode 0: H = gelu(X @ W1 + b1)        (A = g_X [rows,D], B = W1h [D,H])
// mode 1: out[tok] += gate*(H @ W2+b2) (A = g_Hb [rows,H], B = W2h [H,D])
// 8 warps as 4(M) x 2(N); warp tile 32x64; mma m16n8k16.
// ---------------------------------------------------------------------------
#define GSMEM_BYTES (2 * (ASTAGE + BSTAGE))   // 71680 B

__global__ void __launch_bounds__(256, 2)
moe_gemm_kernel(int mode, const float* __restrict__ bias, float* __restrict__ out) {
    extern __shared__ char dyn_smem[];

    int e = blockIdx.z;
    int cnt = g_cnt[e];
    int row0 = blockIdx.y * BM;
    if (row0 >= cnt) return;
    int valid = cnt - row0;
    int nb0 = blockIdx.x * BN;

    const __half* Ag; const __half* Bg;
    int lda, ldb, Kdim;
    if (mode == 0) {
        Ag = g_X   + (size_t)e * CAP * DIM + (size_t)row0 * DIM;  lda = DIM;
        Bg = g_W1h + (size_t)e * DIM * HID;                       ldb = HID;
        Kdim = DIM;
    } else {
        Ag = g_Hb  + (size_t)e * CAP * HID + (size_t)row0 * HID;  lda = HID;
        Bg = g_W2h + (size_t)e * HID * DIM;                       ldb = DIM;
        Kdim = HID;
    }

    int tid = threadIdx.x;
    int lane = tid & 31;
    int warp = tid >> 5;
    int wm = warp >> 1;              // 0..3  (M groups of 32)
    int wn = warp & 1;               // 0..1  (N groups of 64)

    // ---- smem layout: [A stage0][A stage1][B stage0][B stage1]
    uint32_t smemA = smem_u32(dyn_smem);
    uint32_t smemB = smemA + 2 * ASTAGE;

    // ldmatrix sources (stage-0 base)
    uint32_t aaddr0 = smemA + (uint32_t)(((wm * 32 + (lane & 15)) * LDA + ((lane >> 4) << 3)) * 2);
    uint32_t aaddr1 = aaddr0 + 16 * LDA * 2;
    uint32_t bbase  = smemB + (uint32_t)(((lane & 15) * LDB + wn * 64 + ((lane >> 4) << 3)) * 2);

    // cp.async destinations: A tile 1024 x 16B vecs, B tile 1024 x 16B vecs
    uint32_t adst[4], bdst[4];
    const __half* asrc[4]; const __half* bsrc[4];
#pragma unroll
    for (int i = 0; i < 4; i++) {
        int ca = tid + i * 256;
        int ar = ca >> 3, av = ca & 7;               // 8 vecs per 64-half A row
        adst[i] = smemA + (uint32_t)((ar * LDA + av * 8) * 2);
        asrc[i] = Ag + (size_t)ar * lda + av * 8;
        int br = ca >> 4, bv = ca & 15;              // 16 vecs per 128-half B row
        bdst[i] = smemB + (uint32_t)((br * LDB + bv * 8) * 2);
        bsrc[i] = Bg + (size_t)br * ldb + nb0 + bv * 8;
    }
    const size_t bstep = (size_t)BK * ldb;

    float acc[2][8][4];
#pragma unroll
    for (int mi = 0; mi < 2; mi++)
#pragma unroll
        for (int nj = 0; nj < 8; nj++)
#pragma unroll
            for (int q = 0; q < 4; q++) acc[mi][nj][q] = 0.f;

    auto load_stage = [&](uint32_t aoff, uint32_t boff) {
#pragma unroll
        for (int i = 0; i < 4; i++) cp16(adst[i] + aoff, asrc[i]);
#pragma unroll
        for (int i = 0; i < 4; i++) cp16(bdst[i] + boff, bsrc[i]);
        CP_COMMIT();
#pragma unroll
        for (int i = 0; i < 4; i++) { asrc[i] += BK; bsrc[i] += bstep; }
    };

    int nk = Kdim / BK;              // 16 (GEMM1) or 64 (GEMM2)
    load_stage(0, 0);

    uint32_t consA = 0, consB = 0;             // consumer stage offsets
    uint32_t prodA = ASTAGE, prodB = BSTAGE;   // producer stage offsets
    for (int kt = 0; kt < nk; kt++) {
        CP_WAIT(0);                  // stage (kt&1) fully resident
        __syncthreads();             // and previous compute done on other stage
        if (kt + 1 < nk) {
            load_stage(prodA, prodB);      // overlaps this kt's compute
            prodA ^= ASTAGE; prodB ^= BSTAGE;
        }

        uint32_t aA = aaddr0 + consA, aB = aaddr1 + consA;
        uint32_t bA = bbase + consB;

#pragma unroll
        for (int ks = 0; ks < 4; ks++) {
            const uint32_t ksa = ks * 32;              // 16 halves
            const uint32_t ksb = ks * 16 * LDB * 2;    // 16 rows
            uint32_t af[2][4];
            ldsm_x4(af[0], aA + ksa);
            ldsm_x4(af[1], aB + ksa);
            uint32_t bf[8][2];
#pragma unroll
            for (int j = 0; j < 4; j++) {
                uint32_t r4[4];
                ldsm_x4_t(r4, bA + ksb + j * 32);
                bf[2 * j][0] = r4[0]; bf[2 * j][1] = r4[1];
                bf[2 * j + 1][0] = r4[2]; bf[2 * j + 1][1] = r4[3];
            }
#pragma unroll
            for (int mi = 0; mi < 2; mi++)
#pragma unroll
                for (int nj = 0; nj < 8; nj++)
                    mma16816(acc[mi][nj], af[mi], bf[nj]);
        }
        consA ^= ASTAGE; consB ^= BSTAGE;
    }

    // --- Epilogue. acc[mi][nj]: rows wm*32+mi*16+{lane/4,+8}, cols wn*64+nj*8+(lane%4)*2+{0,1}
    if (mode == 0) {
        const float* bp = bias + (size_t)e * HID + nb0;
#pragma unroll
        for (int mi = 0; mi < 2; mi++) {
            int rb = wm * 32 + mi * 16 + (lane >> 2);
#pragma unroll
            for (int hr = 0; hr < 2; hr++) {
                int r = rb + hr * 8;
                if (r < valid) {
                    size_t rowoff = ((size_t)e * CAP + row0 + r) * HID + nb0;
#pragma unroll
                    for (int nj = 0; nj < 8; nj++) {
                        int colc = wn * 64 + nj * 8 + ((lane & 3) << 1);
                        float v0 = acc[mi][nj][hr * 2 + 0] + bp[colc];
                        float v1 = acc[mi][nj][hr * 2 + 1] + bp[colc + 1];
                        __half2 h2 = __floats2half2_rn(gelu_f(v0), gelu_f(v1));
                        *(__half2*)(g_Hb + rowoff + colc) = h2;
                    }
                }
            }
        }
    } else {
        const float* bp = bias + (size_t)e * DIM + nb0;
#pragma unroll
        for (int mi = 0; mi < 2; mi++) {
            int rb = wm * 32 + mi * 16 + (lane >> 2);
#pragma unroll
            for (int hr = 0; hr < 2; hr++) {
                int r = rb + hr * 8;
                if (r < valid) {
                    int t = g_ptok[e * CAP + row0 + r];
                    float gate = g_pgate[e * CAP + row0 + r];
                    float* orow = out + (size_t)t * DIM + nb0;
#pragma unroll
                    for (int nj = 0; nj < 8; nj++) {
                        int colc = wn * 64 + nj * 8 + ((lane & 3) << 1);
                        float v0 = acc[mi][nj][hr * 2 + 0] + bp[colc];
                        float v1 = acc[mi][nj][hr * 2 + 1] + bp[colc + 1];
                        atomicAdd(orow + colc,     gate * v0);
                        atomicAdd(orow + colc + 1, gate * v1);
                    }
                }
            }
        }
    }
}

// ---------------------------------------------------------------------------
// Launch
// ---------------------------------------------------------------------------
extern "C" void kernel_launch(void* const* d_in, const int* in_sizes, int n_in,
                              void* d_out, int out_size) {
    const float* x  = (const float*)d_in[0];
    const float* Wr = (const float*)d_in[1];
    const float* W1 = (const float*)d_in[2];
    const float* b1 = (const float*)d_in[3];
    const float* W2 = (const float*)d_in[4];
    const float* b2 = (const float*)d_in[5];
    float* out = (float*)d_out;

    static int smem_set = 0;
    if (!smem_set) {
        cudaFuncSetAttribute(moe_gemm_kernel,
                             cudaFuncAttributeMaxDynamicSharedMemorySize,
                             GSMEM_BYTES);
        smem_set = 1;
    }

    zero_cnt_kernel<<<1, 32>>>();
    router_gather_kernel<<<NTOK / 8, 256>>>(x, Wr);
    convert_w_kernel<<<2048 + ZBLK, 256>>>(W1, W2, out);
    moe_gemm_kernel<<<dim3(HID / BN, CAP / BM, NE), 256, GSMEM_BYTES>>>(0, b1, nullptr);
    moe_gemm_kernel<<<dim3(DIM / BN, CAP / BM, NE), 256, GSMEM_BYTES>>>(1, b2, out);
}

// round 9
// speedup vs baseline: 1.5170x; 1.0142x over previous
#include <cuda_runtime.h>
#include <cuda_fp16.h>
#include <cstdint>

// ---------------------------------------------------------------------------
// Problem dims (fixed by the dataset)
// ---------------------------------------------------------------------------
#define NTOK 8192          // B*S tokens
#define DIM  1024          // model dim
#define HID  4096          // hidden dim
#define NE   8             // experts
#define CAP  8192          // per-expert token capacity (max possible)

#define BM 128
#define BN 128
#define BK 64
#define LDA (BK + 8)       // 72 halves (144B rows; conflict-free for ldmatrix)
#define LDB (BN + 8)       // 136 halves (272B rows; conflict-free for ldmatrix)
#define ASTAGE (BM * LDA * 2)      // 18432 B per A stage
#define BSTAGE (BK * LDB * 2)      // 17408 B per B stage
// 2 stages: (18432+17408)*2 = 71680 B per CTA -> 2 CTAs/SM

// ---------------------------------------------------------------------------
// Scratch (static __device__ arrays; allocation-free kernel_launch)
// ---------------------------------------------------------------------------
__device__ int    g_cnt[NE];
__device__ int    g_ptok[NE * CAP];
__device__ float  g_pgate[NE * CAP];
__device__ __half g_X  [(size_t)NE * CAP * DIM];   // gathered tokens, fp16
__device__ __half g_W1h[(size_t)NE * DIM * HID];   // W1 fp16, layout [E][D][H]
__device__ __half g_W2h[(size_t)NE * HID * DIM];   // W2 fp16, layout [E][H][D]
__device__ __half g_Hb [(size_t)NE * CAP * HID];   // gelu(x@W1+b1), fp16

// ---------------------------------------------------------------------------
// PTX helpers (baseline compute_103-legal only: cp.async / ldmatrix / mma.sync)
// ---------------------------------------------------------------------------
__device__ __forceinline__ uint32_t smem_u32(const void* p) {
    uint32_t a;
    asm("{ .reg .u64 t; cvta.to.shared.u64 t, %1; cvt.u32.u64 %0, t; }"
        : "=r"(a) : "l"(p));
    return a;
}

__device__ __forceinline__ void cp16(uint32_t smaddr, const void* g) {
    asm volatile("cp.async.cg.shared.global [%0], [%1], 16;"
                 :: "r"(smaddr), "l"(g));
}
#define CP_COMMIT() asm volatile("cp.async.commit_group;" ::: "memory")
#define CP_WAIT(n)  asm volatile("cp.async.wait_group %0;" :: "n"(n) : "memory")

__device__ __forceinline__ void ldsm_x4(uint32_t* r, uint32_t addr) {
    asm volatile("ldmatrix.sync.aligned.m8n8.x4.shared.b16 {%0,%1,%2,%3}, [%4];"
                 : "=r"(r[0]), "=r"(r[1]), "=r"(r[2]), "=r"(r[3]) : "r"(addr));
}
__device__ __forceinline__ void ldsm_x4_t(uint32_t* r, uint32_t addr) {
    asm volatile("ldmatrix.sync.aligned.m8n8.x4.trans.shared.b16 {%0,%1,%2,%3}, [%4];"
                 : "=r"(r[0]), "=r"(r[1]), "=r"(r[2]), "=r"(r[3]) : "r"(addr));
}

__device__ __forceinline__ void mma16816(float* c, const uint32_t* a, const uint32_t* b) {
    asm volatile(
        "mma.sync.aligned.m16n8k16.row.col.f32.f16.f16.f32 "
        "{%0,%1,%2,%3}, {%4,%5,%6,%7}, {%8,%9}, {%0,%1,%2,%3};"
        : "+f"(c[0]), "+f"(c[1]), "+f"(c[2]), "+f"(c[3])
        : "r"(a[0]), "r"(a[1]), "r"(a[2]), "r"(a[3]), "r"(b[0]), "r"(b[1]));
}

// tanh-approximate GELU (JAX default): x * sigmoid(2u), u = 0.79788(x+0.044715x^3)
__device__ __forceinline__ float gelu_f(float v) {
    float u2 = 2.0f * 0.7978845608028654f * (v + 0.044715f * v * v * v);
    u2 = fminf(fmaxf(u2, -30.0f), 30.0f);
    float t = __expf(u2);
    return v * __fdividef(t, t + 1.0f);
}

// ---------------------------------------------------------------------------
// Kernel 1: zero expert counters (must precede router only)
// ---------------------------------------------------------------------------
__global__ void zero_cnt_kernel() {
    if (threadIdx.x < NE) g_cnt[threadIdx.x] = 0;
}

// ---------------------------------------------------------------------------
// Kernel 2: fused router + gather — one warp per token.
// ---------------------------------------------------------------------------
__global__ void router_gather_kernel(const float* __restrict__ x,
                                     const float* __restrict__ Wr) {
    int gwarp = (blockIdx.x * blockDim.x + threadIdx.x) >> 5;
    int lane = threadIdx.x & 31;
    if (gwarp >= NTOK) return;
    const float* xr = x + (size_t)gwarp * DIM;
    float a0 = 0, a1 = 0, a2 = 0, a3 = 0, a4 = 0, a5 = 0, a6 = 0, a7 = 0;
    for (int d = lane; d < DIM; d += 32) {
        float xv = xr[d];
        const float4* w = (const float4*)(Wr + (size_t)d * NE);
        float4 w0 = w[0], w1 = w[1];
        a0 += xv * w0.x; a1 += xv * w0.y; a2 += xv * w0.z; a3 += xv * w0.w;
        a4 += xv * w1.x; a5 += xv * w1.y; a6 += xv * w1.z; a7 += xv * w1.w;
    }
#pragma unroll
    for (int o = 16; o > 0; o >>= 1) {
        a0 += __shfl_xor_sync(0xffffffffu, a0, o);
        a1 += __shfl_xor_sync(0xffffffffu, a1, o);
        a2 += __shfl_xor_sync(0xffffffffu, a2, o);
        a3 += __shfl_xor_sync(0xffffffffu, a3, o);
        a4 += __shfl_xor_sync(0xffffffffu, a4, o);
        a5 += __shfl_xor_sync(0xffffffffu, a5, o);
        a6 += __shfl_xor_sync(0xffffffffu, a6, o);
        a7 += __shfl_xor_sync(0xffffffffu, a7, o);
    }
    int i1 = 0, i2 = 0, s1 = 0, s2 = 0;
    if (lane == 0) {
        float p[8] = {a0, a1, a2, a3, a4, a5, a6, a7};
        float m = p[0];
#pragma unroll
        for (int e = 1; e < 8; e++) m = fmaxf(m, p[e]);
        float s = 0.f;
#pragma unroll
        for (int e = 0; e < 8; e++) { p[e] = expf(p[e] - m); s += p[e]; }
        float inv = 1.0f / s;
#pragma unroll
        for (int e = 0; e < 8; e++) p[e] *= inv;
        float v1 = p[0]; i1 = 0;
#pragma unroll
        for (int e = 1; e < 8; e++) if (p[e] > v1) { v1 = p[e]; i1 = e; }
        float v2 = -1.0f; i2 = -1;
#pragma unroll
        for (int e = 0; e < 8; e++)
            if (e != i1 && p[e] > v2) { v2 = p[e]; i2 = e; }
        s1 = atomicAdd(&g_cnt[i1], 1);
        g_ptok[i1 * CAP + s1] = gwarp; g_pgate[i1 * CAP + s1] = v1;
        s2 = atomicAdd(&g_cnt[i2], 1);
        g_ptok[i2 * CAP + s2] = gwarp; g_pgate[i2 * CAP + s2] = v2;
    }
    i1 = __shfl_sync(0xffffffffu, i1, 0);
    i2 = __shfl_sync(0xffffffffu, i2, 0);
    s1 = __shfl_sync(0xffffffffu, s1, 0);
    s2 = __shfl_sync(0xffffffffu, s2, 0);

    unsigned* d1 = (unsigned*)(g_X + ((size_t)i1 * CAP + s1) * DIM);
    unsigned* d2 = (unsigned*)(g_X + ((size_t)i2 * CAP + s2) * DIM);
    const float2* xf2 = (const float2*)xr;
#pragma unroll
    for (int i = 0; i < 16; i++) {
        int j = lane + i * 32;               // half2 index, 512 per row
        float2 v = __ldg(&xf2[j]);
        __half2 h = __floats2half2_rn(v.x, v.y);
        unsigned u = *reinterpret_cast<unsigned*>(&h);
        d1[j] = u; d2[j] = u;
    }
}

// ---------------------------------------------------------------------------
// Kernel 3: fp32 -> fp16 weight convert + zero `out`.
// ---------------------------------------------------------------------------
#define ZBLK 128
__global__ void convert_w_kernel(const float* __restrict__ W1,
                                 const float* __restrict__ W2,
                                 float* __restrict__ out) {
    if (blockIdx.x < ZBLK) {
        size_t n4 = (size_t)NTOK * DIM / 4;
        size_t stride = (size_t)ZBLK * blockDim.x;
        float4 z = make_float4(0.f, 0.f, 0.f, 0.f);
        for (size_t i = (size_t)blockIdx.x * blockDim.x + threadIdx.x; i < n4; i += stride)
            ((float4*)out)[i] = z;
        return;
    }
    int nb = gridDim.x - ZBLK;
    size_t n4 = (size_t)NE * DIM * HID / 4;
    size_t stride = (size_t)nb * blockDim.x;
    for (size_t i = (size_t)(blockIdx.x - ZBLK) * blockDim.x + threadIdx.x; i < n4; i += stride) {
        float4 v1 = ((const float4*)W1)[i];
        float4 v2 = ((const float4*)W2)[i];
        __half2 a0 = __floats2half2_rn(v1.x, v1.y);
        __half2 a1 = __floats2half2_rn(v1.z, v1.w);
        __half2 b0 = __floats2half2_rn(v2.x, v2.y);
        __half2 b1 = __floats2half2_rn(v2.z, v2.w);
        uint2 u1, u2;
        u1.x = *reinterpret_cast<unsigned*>(&a0);
        u1.y = *reinterpret_cast<unsigned*>(&a1);
        u2.x = *reinterpret_cast<unsigned*>(&b0);
        u2.y = *reinterpret_cast<unsigned*>(&b1);
        ((uint2*)g_W1h)[i] = u1;
        ((uint2*)g_W2h)[i] = u2;
    }
}

// ---------------------------------------------------------------------------
// Kernel 4: fp16 mma.sync GEMM, 128x128x64 tiles, 2-stage double buffer.
// 4 warps as 2(M) x 2(N); warp tile 64x64 (squarer -> 33% less smem fragment
// traffic per output). 128 thr/CTA, 2 CTAs/SM, ~255-reg headroom lets ptxas
// pipeline LDSM under the 32-HMMA trains.
// mode 0: H = gelu(X @ W1 + b1)        (A = g_X [rows,D], B = W1h [D,H])
// mode 1: out[tok] += gate*(H @ W2+b2) (A = g_Hb [rows,H], B = W2h [H,D])
// ---------------------------------------------------------------------------
#define GSMEM_BYTES (2 * (ASTAGE + BSTAGE))   // 71680 B

__global__ void __launch_bounds__(128, 2)
moe_gemm_kernel(int mode, const float* __restrict__ bias, float* __restrict__ out) {
    extern __shared__ char dyn_smem[];

    int e = blockIdx.z;
    int cnt = g_cnt[e];
    int row0 = blockIdx.y * BM;
    if (row0 >= cnt) return;
    int valid = cnt - row0;
    int nb0 = blockIdx.x * BN;

    const __half* Ag; const __half* Bg;
    int lda, ldb, Kdim;
    if (mode == 0) {
        Ag = g_X   + (size_t)e * CAP * DIM + (size_t)row0 * DIM;  lda = DIM;
        Bg = g_W1h + (size_t)e * DIM * HID;                       ldb = HID;
        Kdim = DIM;
    } else {
        Ag = g_Hb  + (size_t)e * CAP * HID + (size_t)row0 * HID;  lda = HID;
        Bg = g_W2h + (size_t)e * HID * DIM;                       ldb = DIM;
        Kdim = HID;
    }

    int tid = threadIdx.x;
    int lane = tid & 31;
    int warp = tid >> 5;
    int wm = warp >> 1;              // 0..1  (M groups of 64)
    int wn = warp & 1;               // 0..1  (N groups of 64)

    // ---- smem layout: [A stage0][A stage1][B stage0][B stage1]
    uint32_t smemA = smem_u32(dyn_smem);
    uint32_t smemB = smemA + 2 * ASTAGE;

    // ldmatrix sources (stage-0 base); per-mi stride 16*LDA*2, per-ks +32B
    uint32_t aaddr = smemA + (uint32_t)(((wm * 64 + (lane & 15)) * LDA + ((lane >> 4) << 3)) * 2);
    uint32_t bbase = smemB + (uint32_t)(((lane & 15) * LDB + wn * 64 + ((lane >> 4) << 3)) * 2);

    // cp.async: A tile 1024 x 16B vecs, B tile 1024 x 16B vecs; 8+8 per thread
    uint32_t adst = smemA + (uint32_t)((((tid >> 3)) * LDA + (tid & 7) * 8) * 2);
    uint32_t bdst = smemB + (uint32_t)((((tid >> 4)) * LDB + (tid & 15) * 8) * 2);
    const __half* asrcp = Ag + (size_t)(tid >> 3) * lda + (tid & 7) * 8;
    const __half* bsrcp = Bg + (size_t)(tid >> 4) * ldb + nb0 + (tid & 15) * 8;
    const int a16 = 16 * lda;        // 16-row global stride (halves)
    const int b8  = 8 * ldb;         // 8-row global stride (halves)

    float acc[4][8][4];
#pragma unroll
    for (int mi = 0; mi < 4; mi++)
#pragma unroll
        for (int nj = 0; nj < 8; nj++)
#pragma unroll
            for (int q = 0; q < 4; q++) acc[mi][nj][q] = 0.f;

    auto load_stage = [&](uint32_t aoff, uint32_t boff) {
#pragma unroll
        for (int p = 0; p < 8; p++)
            cp16(adst + aoff + p * (16 * LDA * 2), asrcp + (size_t)p * a16);
#pragma unroll
        for (int p = 0; p < 8; p++)
            cp16(bdst + boff + p * (8 * LDB * 2), bsrcp + (size_t)p * b8);
        CP_COMMIT();
        asrcp += BK;
        bsrcp += (size_t)BK * ldb;
    };

    int nk = Kdim / BK;              // 16 (GEMM1) or 64 (GEMM2)
    load_stage(0, 0);

    uint32_t consA = 0, consB = 0;
    uint32_t prodA = ASTAGE, prodB = BSTAGE;
    for (int kt = 0; kt < nk; kt++) {
        CP_WAIT(0);
        __syncthreads();
        if (kt + 1 < nk) {
            load_stage(prodA, prodB);      // overlaps this kt's compute
            prodA ^= ASTAGE; prodB ^= BSTAGE;
        }

        uint32_t aA = aaddr + consA;
        uint32_t bA = bbase + consB;

#pragma unroll
        for (int ks = 0; ks < 4; ks++) {
            const uint32_t ksa = ks * 32;              // 16 halves
            const uint32_t ksb = ks * 16 * LDB * 2;    // 16 rows
            uint32_t af[4][4];
#pragma unroll
            for (int mi = 0; mi < 4; mi++)
                ldsm_x4(af[mi], aA + ksa + mi * (16 * LDA * 2));
            uint32_t bf[8][2];
#pragma unroll
            for (int j = 0; j < 4; j++) {
                uint32_t r4[4];
                ldsm_x4_t(r4, bA + ksb + j * 32);
                bf[2 * j][0] = r4[0]; bf[2 * j][1] = r4[1];
                bf[2 * j + 1][0] = r4[2]; bf[2 * j + 1][1] = r4[3];
            }
#pragma unroll
            for (int mi = 0; mi < 4; mi++)
#pragma unroll
                for (int nj = 0; nj < 8; nj++)
                    mma16816(acc[mi][nj], af[mi], bf[nj]);
        }
        consA ^= ASTAGE; consB ^= BSTAGE;
    }

    // --- Epilogue. acc[mi][nj]: rows wm*64+mi*16+{lane/4,+8}, cols wn*64+nj*8+(lane%4)*2+{0,1}
    if (mode == 0) {
        const float* bp = bias + (size_t)e * HID + nb0;
#pragma unroll
        for (int mi = 0; mi < 4; mi++) {
            int rb = wm * 64 + mi * 16 + (lane >> 2);
#pragma unroll
            for (int hr = 0; hr < 2; hr++) {
                int r = rb + hr * 8;
                if (r < valid) {
                    size_t rowoff = ((size_t)e * CAP + row0 + r) * HID + nb0;
#pragma unroll
                    for (int nj = 0; nj < 8; nj++) {
                        int colc = wn * 64 + nj * 8 + ((lane & 3) << 1);
                        float v0 = acc[mi][nj][hr * 2 + 0] + bp[colc];
                        float v1 = acc[mi][nj][hr * 2 + 1] + bp[colc + 1];
                        __half2 h2 = __floats2half2_rn(gelu_f(v0), gelu_f(v1));
                        *(__half2*)(g_Hb + rowoff + colc) = h2;
                    }
                }
            }
        }
    } else {
        const float* bp = bias + (size_t)e * DIM + nb0;
#pragma unroll
        for (int mi = 0; mi < 4; mi++) {
            int rb = wm * 64 + mi * 16 + (lane >> 2);
#pragma unroll
            for (int hr = 0; hr < 2; hr++) {
                int r = rb + hr * 8;
                if (r < valid) {
                    int t = g_ptok[e * CAP + row0 + r];
                    float gate = g_pgate[e * CAP + row0 + r];
                    float* orow = out + (size_t)t * DIM + nb0;
#pragma unroll
                    for (int nj = 0; nj < 8; nj++) {
                        int colc = wn * 64 + nj * 8 + ((lane & 3) << 1);
                        float v0 = acc[mi][nj][hr * 2 + 0] + bp[colc];
                        float v1 = acc[mi][nj][hr * 2 + 1] + bp[colc + 1];
                        atomicAdd(orow + colc,     gate * v0);
                        atomicAdd(orow + colc + 1, gate * v1);
                    }
                }
            }
        }
    }
}

// ---------------------------------------------------------------------------
// Launch
// ---------------------------------------------------------------------------
extern "C" void kernel_launch(void* const* d_in, const int* in_sizes, int n_in,
                              void* d_out, int out_size) {
    const float* x  = (const float*)d_in[0];
    const float* Wr = (const float*)d_in[1];
    const float* W1 = (const float*)d_in[2];
    const float* b1 = (const float*)d_in[3];
    const float* W2 = (const float*)d_in[4];
    const float* b2 = (const float*)d_in[5];
    float* out = (float*)d_out;

    static int smem_set = 0;
    if (!smem_set) {
        cudaFuncSetAttribute(moe_gemm_kernel,
                             cudaFuncAttributeMaxDynamicSharedMemorySize,
                             GSMEM_BYTES);
        smem_set = 1;
    }

    zero_cnt_kernel<<<1, 32>>>();
    router_gather_kernel<<<NTOK / 8, 256>>>(x, Wr);
    convert_w_kernel<<<2048 + ZBLK, 256>>>(W1, W2, out);
    moe_gemm_kernel<<<dim3(HID / BN, CAP / BM, NE), 128, GSMEM_BYTES>>>(0, b1, nullptr);
    moe_gemm_kernel<<<dim3(DIM / BN, CAP / BM, NE), 128, GSMEM_BYTES>>>(1, b2, out);
}